// round 1
// baseline (speedup 1.0000x reference)
#include <cuda_runtime.h>
#include <math.h>

#define B_ 2
#define L_ 2048
#define C_ 1024
#define H_ 16
#define M_ 4096   // B_*L_

// ---------------- scratch (static device globals; no allocation) ----------------
__device__ float g_mod6[B_ * 6 * C_];          // adaLN modulation outputs [B, 6C]
__device__ float g_h[M_ * C_];                 // LN+mod activations
__device__ float g_qkv[M_ * 3 * C_];           // qkv projections
__device__ float g_s[134217728];               // attention scores [B*H, L, L] (512MB)
__device__ float g_o[M_ * C_];                 // attention output
__device__ float g_x[M_ * C_];                 // residual stream after MSA
__device__ float g_g[M_ * 4 * C_];             // fc1 output

// ---------------- adaLN modulation: silu(mod) @ w_mod + b_mod ----------------
__global__ void mod_kernel(const float* __restrict__ mod,
                           const float* __restrict__ w,
                           const float* __restrict__ b,
                           float* __restrict__ out) {
    __shared__ float sm[C_];
    int batch = blockIdx.y;
    const float* mrow = mod + batch * C_;
    for (int i = threadIdx.x; i < C_; i += blockDim.x) {
        float v = mrow[i];
        sm[i] = v / (1.0f + expf(-v));
    }
    __syncthreads();
    int n = blockIdx.x * blockDim.x + threadIdx.x;   // 0..6143
    float acc = b[n];
    for (int k = 0; k < C_; k++)
        acc += sm[k] * w[k * (6 * C_) + n];
    out[batch * (6 * C_) + n] = acc;
}

// ---------------- LayerNorm (no affine, eps=1e-6) + shift/scale modulation ----------------
__global__ void ln_mod_kernel(const float* __restrict__ x, float* __restrict__ out,
                              const float* __restrict__ mod6, int shiftChunk, int scaleChunk) {
    __shared__ float red[8];
    __shared__ float bc[2];
    int r = blockIdx.x;
    int b = r >> 11;               // r / L_
    const float* xr = x + (size_t)r * C_;
    int t = threadIdx.x;
    float v[4];
    float s = 0.0f;
#pragma unroll
    for (int i = 0; i < 4; i++) { v[i] = xr[t + 256 * i]; s += v[i]; }
    for (int o = 16; o > 0; o >>= 1) s += __shfl_xor_sync(0xffffffffu, s, o);
    if ((t & 31) == 0) red[t >> 5] = s;
    __syncthreads();
    if (t == 0) {
        float tot = 0.0f;
        for (int i = 0; i < 8; i++) tot += red[i];
        bc[0] = tot * (1.0f / C_);
    }
    __syncthreads();
    float mean = bc[0];
    float q = 0.0f;
#pragma unroll
    for (int i = 0; i < 4; i++) { float d = v[i] - mean; q += d * d; }
    for (int o = 16; o > 0; o >>= 1) q += __shfl_xor_sync(0xffffffffu, q, o);
    __syncthreads();
    if ((t & 31) == 0) red[t >> 5] = q;
    __syncthreads();
    if (t == 0) {
        float tot = 0.0f;
        for (int i = 0; i < 8; i++) tot += red[i];
        bc[1] = rsqrtf(tot * (1.0f / C_) + 1e-6f);
    }
    __syncthreads();
    float rstd = bc[1];
    const float* mb = mod6 + b * (6 * C_);
    float* orow = out + (size_t)r * C_;
#pragma unroll
    for (int i = 0; i < 4; i++) {
        int c = t + 256 * i;
        float sc = mb[scaleChunk * C_ + c];
        float sh = mb[shiftChunk * C_ + c];
        orow[c] = (v[i] - mean) * rstd * (1.0f + sc) + sh;
    }
}

// ---------------- row softmax with 1/sqrt(D) scale ----------------
__global__ void softmax_kernel(float* __restrict__ s) {
    __shared__ float red[8];
    __shared__ float bc;
    size_t r = blockIdx.x;
    float* row = s + r * (size_t)L_;
    int t = threadIdx.x;
    float v[8];
    float mx = -1e30f;
#pragma unroll
    for (int i = 0; i < 8; i++) {
        v[i] = row[t + 256 * i] * 0.125f;   // 1/sqrt(64)
        mx = fmaxf(mx, v[i]);
    }
    for (int o = 16; o > 0; o >>= 1) mx = fmaxf(mx, __shfl_xor_sync(0xffffffffu, mx, o));
    if ((t & 31) == 0) red[t >> 5] = mx;
    __syncthreads();
    if (t == 0) {
        float m = red[0];
        for (int i = 1; i < 8; i++) m = fmaxf(m, red[i]);
        bc = m;
    }
    __syncthreads();
    mx = bc;
    float sum = 0.0f;
#pragma unroll
    for (int i = 0; i < 8; i++) { v[i] = expf(v[i] - mx); sum += v[i]; }
    for (int o = 16; o > 0; o >>= 1) sum += __shfl_xor_sync(0xffffffffu, sum, o);
    __syncthreads();
    if ((t & 31) == 0) red[t >> 5] = sum;
    __syncthreads();
    if (t == 0) {
        float tot = 0.0f;
        for (int i = 0; i < 8; i++) tot += red[i];
        bc = tot;
    }
    __syncthreads();
    float inv = 1.0f / bc;
#pragma unroll
    for (int i = 0; i < 8; i++) row[t + 256 * i] = v[i] * inv;
}

// ---------------- generic tiled SGEMM with fused epilogues ----------------
__device__ __forceinline__ float gelu_f(float x) {
    return 0.5f * x * (1.0f + erff(x * 0.70710678118654752f));
}

// EPI: 0 = none, 1 = +bias, 2 = gelu(+bias), 3 = xin + (acc+bias)*gate  (gated residual)
// TB : false -> C = A(MxK) @ B(KxN row-major);  true -> C = A @ B^T with B (NxK row-major)
template <bool TB, int EPI>
__global__ void __launch_bounds__(256) gemm_kernel(
    const float* __restrict__ A, const float* __restrict__ Bm,
    const float* __restrict__ bias, const float* __restrict__ xin,
    const float* __restrict__ gate, float* __restrict__ Cm,
    int M, int N, int K, int lda, int ldb, int ldc,
    long long sAb, long long sAh, long long sBb, long long sBh,
    long long sCb, long long sCh, int hpb) {
    const int BM = 128, BN = 128, BK = 8;
    __shared__ float As[BK][BM];
    __shared__ float Bs[BK][BN];
    if (hpb) {
        int z = blockIdx.z;
        long long zb = z / hpb, zh = z % hpb;
        A  += zb * sAb + zh * sAh;
        Bm += zb * sBb + zh * sBh;
        Cm += zb * sCb + zh * sCh;
    }
    int bm = blockIdx.y * BM, bn = blockIdx.x * BN;
    int tid = threadIdx.x;
    int ty = tid >> 4, tx = tid & 15;
    float acc[8][8] = {};
    int arow = tid >> 1, ak = (tid & 1) * 4;
    for (int kt = 0; kt < K; kt += BK) {
        float4 a4 = *(const float4*)(A + (size_t)(bm + arow) * lda + kt + ak);
        As[ak + 0][arow] = a4.x; As[ak + 1][arow] = a4.y;
        As[ak + 2][arow] = a4.z; As[ak + 3][arow] = a4.w;
        if (TB) {
            float4 b4 = *(const float4*)(Bm + (size_t)(bn + arow) * ldb + kt + ak);
            Bs[ak + 0][arow] = b4.x; Bs[ak + 1][arow] = b4.y;
            Bs[ak + 2][arow] = b4.z; Bs[ak + 3][arow] = b4.w;
        } else {
            int brow = tid >> 5, bc4 = (tid & 31) * 4;
            float4 b4;
            if (bn + bc4 < N)
                b4 = *(const float4*)(Bm + (size_t)(kt + brow) * ldb + bn + bc4);
            else
                b4 = make_float4(0.f, 0.f, 0.f, 0.f);
            *(float4*)&Bs[brow][bc4] = b4;
        }
        __syncthreads();
#pragma unroll
        for (int k = 0; k < BK; k++) {
            float a[8], b[8];
            *(float4*)(a)     = *(const float4*)&As[k][ty * 8];
            *(float4*)(a + 4) = *(const float4*)&As[k][ty * 8 + 4];
            *(float4*)(b)     = *(const float4*)&Bs[k][tx * 8];
            *(float4*)(b + 4) = *(const float4*)&Bs[k][tx * 8 + 4];
#pragma unroll
            for (int i = 0; i < 8; i++)
#pragma unroll
                for (int j = 0; j < 8; j++)
                    acc[i][j] += a[i] * b[j];
        }
        __syncthreads();
    }
#pragma unroll
    for (int i = 0; i < 8; i++) {
        int r = bm + ty * 8 + i;
        int bb = r >> 11;   // token row -> batch (valid for EPI==3 uses)
#pragma unroll
        for (int j = 0; j < 8; j++) {
            int c = bn + tx * 8 + j;
            if (c < N) {
                float v = acc[i][j];
                if (EPI >= 1) v += bias[c];
                if (EPI == 2) v = gelu_f(v);
                if (EPI == 3) v = xin[(size_t)r * ldc + c] + v * gate[bb * (6 * C_) + c];
                Cm[(size_t)r * ldc + c] = v;
            }
        }
    }
}

// ---------------- launch ----------------
extern "C" void kernel_launch(void* const* d_in, const int* in_sizes, int n_in,
                              void* d_out, int out_size) {
    const float* feats  = (const float*)d_in[0];
    const float* mod    = (const float*)d_in[1];
    const float* w_mod  = (const float*)d_in[2];
    const float* b_mod  = (const float*)d_in[3];
    const float* w_qkv  = (const float*)d_in[4];
    const float* b_qkv  = (const float*)d_in[5];
    const float* w_proj = (const float*)d_in[6];
    const float* b_proj = (const float*)d_in[7];
    const float* w_fc1  = (const float*)d_in[8];
    const float* b_fc1  = (const float*)d_in[9];
    const float* w_fc2  = (const float*)d_in[10];
    const float* b_fc2  = (const float*)d_in[11];
    float* out = (float*)d_out;

    float *mod6, *h, *qkv, *sbuf, *obuf, *xbuf, *gbuf;
    cudaGetSymbolAddress((void**)&mod6, g_mod6);
    cudaGetSymbolAddress((void**)&h,    g_h);
    cudaGetSymbolAddress((void**)&qkv,  g_qkv);
    cudaGetSymbolAddress((void**)&sbuf, g_s);
    cudaGetSymbolAddress((void**)&obuf, g_o);
    cudaGetSymbolAddress((void**)&xbuf, g_x);
    cudaGetSymbolAddress((void**)&gbuf, g_g);

    // 1. adaLN modulation vector
    mod_kernel<<<dim3(6 * C_ / 256, B_), 256>>>(mod, w_mod, b_mod, mod6);

    // 2. LN1 + (shift_a, scale_a)
    ln_mod_kernel<<<M_, 256>>>(feats, h, mod6, 0, 1);

    // 3. qkv = h @ w_qkv + b_qkv   [4096 x 3072]
    gemm_kernel<false, 1><<<dim3(24, 32, 1), 256>>>(
        h, w_qkv, b_qkv, nullptr, nullptr, qkv,
        M_, 3 * C_, C_, C_, 3 * C_, 3 * C_,
        0, 0, 0, 0, 0, 0, 0);

    // 4. scores = Q @ K^T per (b,h)  [2048 x 2048] x 32
    gemm_kernel<true, 0><<<dim3(16, 16, B_ * H_), 256>>>(
        qkv, qkv + C_, nullptr, nullptr, nullptr, sbuf,
        L_, L_, 64, 3 * C_, 3 * C_, L_,
        (long long)L_ * 3 * C_, 64,
        (long long)L_ * 3 * C_, 64,
        (long long)H_ * L_ * L_, (long long)L_ * L_, H_);

    // 5. softmax over keys (with 1/8 scale)
    softmax_kernel<<<B_ * H_ * L_, 256>>>(sbuf);

    // 6. O = P @ V per (b,h)  [2048 x 64] x 32
    gemm_kernel<false, 0><<<dim3(1, 16, B_ * H_), 256>>>(
        sbuf, qkv + 2 * C_, nullptr, nullptr, nullptr, obuf,
        L_, 64, L_, L_, 3 * C_, C_,
        (long long)H_ * L_ * L_, (long long)L_ * L_,
        (long long)L_ * 3 * C_, 64,
        (long long)L_ * C_, 64, H_);

    // 7. x = feats + (O @ w_proj + b_proj) * gate_a
    gemm_kernel<false, 3><<<dim3(8, 32, 1), 256>>>(
        obuf, w_proj, b_proj, feats, mod6 + 2 * C_, xbuf,
        M_, C_, C_, C_, C_, C_,
        0, 0, 0, 0, 0, 0, 0);

    // 8. LN2 + (shift_m, scale_m)
    ln_mod_kernel<<<M_, 256>>>(xbuf, h, mod6, 3, 4);

    // 9. g = gelu(h @ w_fc1 + b_fc1)   [4096 x 4096]
    gemm_kernel<false, 2><<<dim3(32, 32, 1), 256>>>(
        h, w_fc1, b_fc1, nullptr, nullptr, gbuf,
        M_, 4 * C_, C_, C_, 4 * C_, 4 * C_,
        0, 0, 0, 0, 0, 0, 0);

    // 10. out = x + (g @ w_fc2 + b_fc2) * gate_m
    gemm_kernel<false, 3><<<dim3(8, 32, 1), 256>>>(
        gbuf, w_fc2, b_fc2, xbuf, mod6 + 5 * C_, out,
        M_, C_, 4 * C_, 4 * C_, C_, C_,
        0, 0, 0, 0, 0, 0, 0);
}

// round 2
// speedup vs baseline: 2.5081x; 2.5081x over previous
#include <cuda_runtime.h>
#include <math.h>
#include <stdint.h>

#define B_ 2
#define L_ 2048
#define C_ 1024
#define H_ 16
#define M_ 4096   // B_*L_

// ---------------- scratch (static device globals; no allocation) ----------------
__device__ float g_mod6[B_ * 6 * C_];          // adaLN modulation outputs [B, 6C]
__device__ float g_h[M_ * C_];                 // LN+mod activations
__device__ float g_qkv[M_ * 3 * C_];           // qkv projections
__device__ float g_s[134217728];               // attention scores [B*H, L, L] (512MB)
__device__ float g_o[M_ * C_];                 // attention output
__device__ float g_x[M_ * C_];                 // residual stream after MSA
__device__ float g_g[M_ * 4 * C_];             // fc1 output

// ---------------- adaLN modulation: silu(mod) @ w_mod + b_mod ----------------
__global__ void mod_kernel(const float* __restrict__ mod,
                           const float* __restrict__ w,
                           const float* __restrict__ b,
                           float* __restrict__ out) {
    __shared__ float sm[C_];
    int batch = blockIdx.y;
    const float* mrow = mod + batch * C_;
    for (int i = threadIdx.x; i < C_; i += blockDim.x) {
        float v = mrow[i];
        sm[i] = v / (1.0f + expf(-v));
    }
    __syncthreads();
    int n = blockIdx.x * blockDim.x + threadIdx.x;
    float acc = b[n];
    for (int k = 0; k < C_; k++)
        acc += sm[k] * w[k * (6 * C_) + n];
    out[batch * (6 * C_) + n] = acc;
}

// ---------------- LayerNorm (no affine, eps=1e-6) + shift/scale modulation ----------------
__global__ void ln_mod_kernel(const float* __restrict__ x, float* __restrict__ out,
                              const float* __restrict__ mod6, int shiftChunk, int scaleChunk) {
    __shared__ float red[8];
    __shared__ float bc[2];
    int r = blockIdx.x;
    int b = r >> 11;
    const float* xr = x + (size_t)r * C_;
    int t = threadIdx.x;
    float v[4];
    float s = 0.0f;
#pragma unroll
    for (int i = 0; i < 4; i++) { v[i] = xr[t + 256 * i]; s += v[i]; }
    for (int o = 16; o > 0; o >>= 1) s += __shfl_xor_sync(0xffffffffu, s, o);
    if ((t & 31) == 0) red[t >> 5] = s;
    __syncthreads();
    if (t == 0) {
        float tot = 0.0f;
        for (int i = 0; i < 8; i++) tot += red[i];
        bc[0] = tot * (1.0f / C_);
    }
    __syncthreads();
    float mean = bc[0];
    float q = 0.0f;
#pragma unroll
    for (int i = 0; i < 4; i++) { float d = v[i] - mean; q += d * d; }
    for (int o = 16; o > 0; o >>= 1) q += __shfl_xor_sync(0xffffffffu, q, o);
    __syncthreads();
    if ((t & 31) == 0) red[t >> 5] = q;
    __syncthreads();
    if (t == 0) {
        float tot = 0.0f;
        for (int i = 0; i < 8; i++) tot += red[i];
        bc[1] = rsqrtf(tot * (1.0f / C_) + 1e-6f);
    }
    __syncthreads();
    float rstd = bc[1];
    const float* mb = mod6 + b * (6 * C_);
    float* orow = out + (size_t)r * C_;
#pragma unroll
    for (int i = 0; i < 4; i++) {
        int c = t + 256 * i;
        float sc = mb[scaleChunk * C_ + c];
        float sh = mb[shiftChunk * C_ + c];
        orow[c] = (v[i] - mean) * rstd * (1.0f + sc) + sh;
    }
}

// ---------------- row softmax with 1/sqrt(D) scale ----------------
__global__ void softmax_kernel(float* __restrict__ s) {
    __shared__ float red[8];
    __shared__ float bc;
    size_t r = blockIdx.x;
    float* row = s + r * (size_t)L_;
    int t = threadIdx.x;
    float v[8];
    float mx = -1e30f;
#pragma unroll
    for (int i = 0; i < 8; i++) {
        v[i] = row[t + 256 * i] * 0.125f;
        mx = fmaxf(mx, v[i]);
    }
    for (int o = 16; o > 0; o >>= 1) mx = fmaxf(mx, __shfl_xor_sync(0xffffffffu, mx, o));
    if ((t & 31) == 0) red[t >> 5] = mx;
    __syncthreads();
    if (t == 0) {
        float m = red[0];
        for (int i = 1; i < 8; i++) m = fmaxf(m, red[i]);
        bc = m;
    }
    __syncthreads();
    mx = bc;
    float sum = 0.0f;
#pragma unroll
    for (int i = 0; i < 8; i++) { v[i] = expf(v[i] - mx); sum += v[i]; }
    for (int o = 16; o > 0; o >>= 1) sum += __shfl_xor_sync(0xffffffffu, sum, o);
    __syncthreads();
    if ((t & 31) == 0) red[t >> 5] = sum;
    __syncthreads();
    if (t == 0) {
        float tot = 0.0f;
        for (int i = 0; i < 8; i++) tot += red[i];
        bc = tot;
    }
    __syncthreads();
    float inv = 1.0f / bc;
#pragma unroll
    for (int i = 0; i < 8; i++) row[t + 256 * i] = v[i] * inv;
}

// ---------------- tf32 tensor-core GEMM ----------------
__device__ __forceinline__ float gelu_f(float x) {
    return 0.5f * x * (1.0f + erff(x * 0.70710678118654752f));
}

__device__ __forceinline__ uint32_t f2tf(float f) {
    uint32_t r;
    asm("cvt.rna.tf32.f32 %0, %1;" : "=r"(r) : "f"(f));
    return r;
}

__device__ __forceinline__ void mma_tf32(float* d, const uint32_t* a, const uint32_t* b) {
    asm volatile(
        "mma.sync.aligned.m16n8k8.row.col.f32.tf32.tf32.f32 "
        "{%0,%1,%2,%3}, {%4,%5,%6,%7}, {%8,%9}, {%0,%1,%2,%3};\n"
        : "+f"(d[0]), "+f"(d[1]), "+f"(d[2]), "+f"(d[3])
        : "r"(a[0]), "r"(a[1]), "r"(a[2]), "r"(a[3]), "r"(b[0]), "r"(b[1]));
}

// EPI: 0 = none, 1 = +bias, 2 = gelu(+bias), 3 = xin + (acc+bias)*gate
// TB : false -> C = A(MxK) @ B(KxN row-major);  true -> C = A @ B^T, B (NxK row-major)
template <bool TB, int EPI>
__global__ void __launch_bounds__(256) gemm_tc(
    const float* __restrict__ A, const float* __restrict__ Bm,
    const float* __restrict__ bias, const float* __restrict__ xin,
    const float* __restrict__ gate, float* __restrict__ Cm,
    int M, int N, int K, int lda, int ldb, int ldc,
    long long sAb, long long sAh, long long sBb, long long sBh,
    long long sCb, long long sCh, int hpb) {
    constexpr int BM = 128, BN = 128, BK = 16;
    constexpr int PAD = 8;
    __shared__ uint32_t As[2][BK][BM + PAD];   // k-major tf32 bits
    __shared__ uint32_t Bs[2][BK][BN + PAD];   // k-major tf32 bits

    if (hpb) {
        int z = blockIdx.z;
        long long zb = z / hpb, zh = z % hpb;
        A  += zb * sAb + zh * sAh;
        Bm += zb * sBb + zh * sBh;
        Cm += zb * sCb + zh * sCh;
    }
    int bm = blockIdx.y * BM, bn = blockIdx.x * BN;
    int tid = threadIdx.x;
    int w = tid >> 5, lane = tid & 31;
    int wm = (w & 1) * 64, wn = (w >> 1) * 32;
    int g = lane >> 2, tq = lane & 3;

    float acc[4][4][4];
#pragma unroll
    for (int i = 0; i < 4; i++)
#pragma unroll
        for (int j = 0; j < 4; j++)
#pragma unroll
            for (int k = 0; k < 4; k++) acc[i][j][k] = 0.0f;

    float4 ra[2], rb[2];

    // ---- global load: A tile 128x16 (512 float4), B tile per TB ----
#define LOADG(kt)                                                                  \
    {                                                                              \
        _Pragma("unroll")                                                          \
        for (int it = 0; it < 2; it++) {                                           \
            int ai = tid * 2 + it;                                                 \
            int arow = ai >> 2, aq = ai & 3;                                       \
            ra[it] = *(const float4*)(A + (size_t)(bm + arow) * lda + (kt) + aq * 4); \
            if (TB) {                                                              \
                rb[it] = *(const float4*)(Bm + (size_t)(bn + arow) * ldb + (kt) + aq * 4); \
            } else {                                                               \
                int brow = ai >> 5, bc4 = ai & 31;                                 \
                int col = bn + bc4 * 4;                                            \
                rb[it] = (col < N)                                                 \
                    ? *(const float4*)(Bm + (size_t)((kt) + brow) * ldb + col)     \
                    : make_float4(0.f, 0.f, 0.f, 0.f);                             \
            }                                                                      \
        }                                                                          \
    }

#define STORES(bf)                                                                 \
    {                                                                              \
        _Pragma("unroll")                                                          \
        for (int it = 0; it < 2; it++) {                                           \
            int ai = tid * 2 + it;                                                 \
            int arow = ai >> 2, aq = ai & 3;                                       \
            As[bf][aq * 4 + 0][arow] = f2tf(ra[it].x);                             \
            As[bf][aq * 4 + 1][arow] = f2tf(ra[it].y);                             \
            As[bf][aq * 4 + 2][arow] = f2tf(ra[it].z);                             \
            As[bf][aq * 4 + 3][arow] = f2tf(ra[it].w);                             \
            if (TB) {                                                              \
                Bs[bf][aq * 4 + 0][arow] = f2tf(rb[it].x);                         \
                Bs[bf][aq * 4 + 1][arow] = f2tf(rb[it].y);                         \
                Bs[bf][aq * 4 + 2][arow] = f2tf(rb[it].z);                         \
                Bs[bf][aq * 4 + 3][arow] = f2tf(rb[it].w);                         \
            } else {                                                               \
                int brow = ai >> 5, bc4 = ai & 31;                                 \
                Bs[bf][brow][bc4 * 4 + 0] = f2tf(rb[it].x);                        \
                Bs[bf][brow][bc4 * 4 + 1] = f2tf(rb[it].y);                        \
                Bs[bf][brow][bc4 * 4 + 2] = f2tf(rb[it].z);                        \
                Bs[bf][brow][bc4 * 4 + 3] = f2tf(rb[it].w);                        \
            }                                                                      \
        }                                                                          \
    }

#define COMP(bf)                                                                   \
    {                                                                              \
        _Pragma("unroll")                                                          \
        for (int k0 = 0; k0 < BK; k0 += 8) {                                       \
            uint32_t af[4][4], bfr[4][2];                                          \
            _Pragma("unroll")                                                      \
            for (int mt = 0; mt < 4; mt++) {                                       \
                int r = wm + mt * 16 + g;                                          \
                af[mt][0] = As[bf][k0 + tq][r];                                    \
                af[mt][1] = As[bf][k0 + tq][r + 8];                                \
                af[mt][2] = As[bf][k0 + tq + 4][r];                                \
                af[mt][3] = As[bf][k0 + tq + 4][r + 8];                            \
            }                                                                      \
            _Pragma("unroll")                                                      \
            for (int nt = 0; nt < 4; nt++) {                                       \
                int c = wn + nt * 8 + g;                                           \
                bfr[nt][0] = Bs[bf][k0 + tq][c];                                   \
                bfr[nt][1] = Bs[bf][k0 + tq + 4][c];                               \
            }                                                                      \
            _Pragma("unroll")                                                      \
            for (int mt = 0; mt < 4; mt++)                                         \
                _Pragma("unroll")                                                  \
                for (int nt = 0; nt < 4; nt++)                                     \
                    mma_tf32(acc[mt][nt], af[mt], bfr[nt]);                        \
        }                                                                          \
    }

    LOADG(0);
    STORES(0);
    __syncthreads();
    int buf = 0;
    for (int kt = BK; kt < K; kt += BK) {
        LOADG(kt);
        COMP(buf);
        __syncthreads();
        STORES(buf ^ 1);
        __syncthreads();
        buf ^= 1;
    }
    COMP(buf);

    // ---- epilogue ----
#pragma unroll
    for (int mt = 0; mt < 4; mt++) {
#pragma unroll
        for (int i = 0; i < 2; i++) {
            int r = bm + wm + mt * 16 + g + i * 8;
            int bb = r >> 11;
#pragma unroll
            for (int nt = 0; nt < 4; nt++) {
                int c = bn + wn + nt * 8 + tq * 2;
                if (c < N) {
                    float v0 = acc[mt][nt][i * 2 + 0];
                    float v1 = acc[mt][nt][i * 2 + 1];
                    if (EPI >= 1) { v0 += bias[c]; v1 += bias[c + 1]; }
                    if (EPI == 2) { v0 = gelu_f(v0); v1 = gelu_f(v1); }
                    if (EPI == 3) {
                        v0 = xin[(size_t)r * ldc + c]     + v0 * gate[bb * (6 * C_) + c];
                        v1 = xin[(size_t)r * ldc + c + 1] + v1 * gate[bb * (6 * C_) + c + 1];
                    }
                    Cm[(size_t)r * ldc + c]     = v0;
                    Cm[(size_t)r * ldc + c + 1] = v1;
                }
            }
        }
    }
#undef LOADG
#undef STORES
#undef COMP
}

// ---------------- launch ----------------
extern "C" void kernel_launch(void* const* d_in, const int* in_sizes, int n_in,
                              void* d_out, int out_size) {
    const float* feats  = (const float*)d_in[0];
    const float* mod    = (const float*)d_in[1];
    const float* w_mod  = (const float*)d_in[2];
    const float* b_mod  = (const float*)d_in[3];
    const float* w_qkv  = (const float*)d_in[4];
    const float* b_qkv  = (const float*)d_in[5];
    const float* w_proj = (const float*)d_in[6];
    const float* b_proj = (const float*)d_in[7];
    const float* w_fc1  = (const float*)d_in[8];
    const float* b_fc1  = (const float*)d_in[9];
    const float* w_fc2  = (const float*)d_in[10];
    const float* b_fc2  = (const float*)d_in[11];
    float* out = (float*)d_out;

    float *mod6, *h, *qkv, *sbuf, *obuf, *xbuf, *gbuf;
    cudaGetSymbolAddress((void**)&mod6, g_mod6);
    cudaGetSymbolAddress((void**)&h,    g_h);
    cudaGetSymbolAddress((void**)&qkv,  g_qkv);
    cudaGetSymbolAddress((void**)&sbuf, g_s);
    cudaGetSymbolAddress((void**)&obuf, g_o);
    cudaGetSymbolAddress((void**)&xbuf, g_x);
    cudaGetSymbolAddress((void**)&gbuf, g_g);

    // 1. adaLN modulation vector
    mod_kernel<<<dim3(6 * C_ / 256, B_), 256>>>(mod, w_mod, b_mod, mod6);

    // 2. LN1 + (shift_a, scale_a)
    ln_mod_kernel<<<M_, 256>>>(feats, h, mod6, 0, 1);

    // 3. qkv = h @ w_qkv + b_qkv   [4096 x 3072]
    gemm_tc<false, 1><<<dim3(24, 32, 1), 256>>>(
        h, w_qkv, b_qkv, nullptr, nullptr, qkv,
        M_, 3 * C_, C_, C_, 3 * C_, 3 * C_,
        0, 0, 0, 0, 0, 0, 0);

    // 4. scores = Q @ K^T per (b,h)  [2048 x 2048] x 32
    gemm_tc<true, 0><<<dim3(16, 16, B_ * H_), 256>>>(
        qkv, qkv + C_, nullptr, nullptr, nullptr, sbuf,
        L_, L_, 64, 3 * C_, 3 * C_, L_,
        (long long)L_ * 3 * C_, 64,
        (long long)L_ * 3 * C_, 64,
        (long long)H_ * L_ * L_, (long long)L_ * L_, H_);

    // 5. softmax over keys (with 1/8 scale)
    softmax_kernel<<<B_ * H_ * L_, 256>>>(sbuf);

    // 6. O = P @ V per (b,h)  [2048 x 64] x 32
    gemm_tc<false, 0><<<dim3(1, 16, B_ * H_), 256>>>(
        sbuf, qkv + 2 * C_, nullptr, nullptr, nullptr, obuf,
        L_, 64, L_, L_, 3 * C_, C_,
        (long long)H_ * L_ * L_, (long long)L_ * L_,
        (long long)L_ * 3 * C_, 64,
        (long long)L_ * C_, 64, H_);

    // 7. x = feats + (O @ w_proj + b_proj) * gate_a
    gemm_tc<false, 3><<<dim3(8, 32, 1), 256>>>(
        obuf, w_proj, b_proj, feats, mod6 + 2 * C_, xbuf,
        M_, C_, C_, C_, C_, C_,
        0, 0, 0, 0, 0, 0, 0);

    // 8. LN2 + (shift_m, scale_m)
    ln_mod_kernel<<<M_, 256>>>(xbuf, h, mod6, 3, 4);

    // 9. g = gelu(h @ w_fc1 + b_fc1)   [4096 x 4096]
    gemm_tc<false, 2><<<dim3(32, 32, 1), 256>>>(
        h, w_fc1, b_fc1, nullptr, nullptr, gbuf,
        M_, 4 * C_, C_, C_, 4 * C_, 4 * C_,
        0, 0, 0, 0, 0, 0, 0);

    // 10. out = x + (g @ w_fc2 + b_fc2) * gate_m
    gemm_tc<false, 3><<<dim3(8, 32, 1), 256>>>(
        gbuf, w_fc2, b_fc2, xbuf, mod6 + 5 * C_, out,
        M_, C_, 4 * C_, 4 * C_, C_, C_,
        0, 0, 0, 0, 0, 0, 0);
}

// round 3
// speedup vs baseline: 2.9821x; 1.1890x over previous
#include <cuda_runtime.h>
#include <math.h>
#include <stdint.h>

#define B_ 2
#define L_ 2048
#define C_ 1024
#define H_ 16
#define M_ 4096   // B_*L_

// ---------------- scratch (static device globals; no allocation) ----------------
__device__ float g_mod6[B_ * 6 * C_];          // adaLN modulation outputs [B, 6C]
__device__ float g_h[M_ * C_];                 // LN+mod activations
__device__ float g_qkv[M_ * 3 * C_];           // qkv projections
__device__ float g_o[M_ * C_];                 // attention output
__device__ float g_x[M_ * C_];                 // residual stream after MSA
__device__ float g_g[M_ * 4 * C_];             // fc1 output

// ---------------- adaLN modulation: silu(mod) @ w_mod + b_mod ----------------
__global__ void mod_kernel(const float* __restrict__ mod,
                           const float* __restrict__ w,
                           const float* __restrict__ b,
                           float* __restrict__ out) {
    __shared__ float sm[C_];
    int batch = blockIdx.y;
    const float* mrow = mod + batch * C_;
    for (int i = threadIdx.x; i < C_; i += blockDim.x) {
        float v = mrow[i];
        sm[i] = v / (1.0f + expf(-v));
    }
    __syncthreads();
    int n = blockIdx.x * blockDim.x + threadIdx.x;
    float acc = b[n];
    for (int k = 0; k < C_; k++)
        acc += sm[k] * w[k * (6 * C_) + n];
    out[batch * (6 * C_) + n] = acc;
}

// ---------------- LayerNorm (no affine, eps=1e-6) + shift/scale modulation ----------------
__global__ void ln_mod_kernel(const float* __restrict__ x, float* __restrict__ out,
                              const float* __restrict__ mod6, int shiftChunk, int scaleChunk) {
    __shared__ float red[8];
    __shared__ float bc[2];
    int r = blockIdx.x;
    int b = r >> 11;
    const float* xr = x + (size_t)r * C_;
    int t = threadIdx.x;
    float v[4];
    float s = 0.0f;
#pragma unroll
    for (int i = 0; i < 4; i++) { v[i] = xr[t + 256 * i]; s += v[i]; }
    for (int o = 16; o > 0; o >>= 1) s += __shfl_xor_sync(0xffffffffu, s, o);
    if ((t & 31) == 0) red[t >> 5] = s;
    __syncthreads();
    if (t == 0) {
        float tot = 0.0f;
        for (int i = 0; i < 8; i++) tot += red[i];
        bc[0] = tot * (1.0f / C_);
    }
    __syncthreads();
    float mean = bc[0];
    float q = 0.0f;
#pragma unroll
    for (int i = 0; i < 4; i++) { float d = v[i] - mean; q += d * d; }
    for (int o = 16; o > 0; o >>= 1) q += __shfl_xor_sync(0xffffffffu, q, o);
    __syncthreads();
    if ((t & 31) == 0) red[t >> 5] = q;
    __syncthreads();
    if (t == 0) {
        float tot = 0.0f;
        for (int i = 0; i < 8; i++) tot += red[i];
        bc[1] = rsqrtf(tot * (1.0f / C_) + 1e-6f);
    }
    __syncthreads();
    float rstd = bc[1];
    const float* mb = mod6 + b * (6 * C_);
    float* orow = out + (size_t)r * C_;
#pragma unroll
    for (int i = 0; i < 4; i++) {
        int c = t + 256 * i;
        float sc = mb[scaleChunk * C_ + c];
        float sh = mb[shiftChunk * C_ + c];
        orow[c] = (v[i] - mean) * rstd * (1.0f + sc) + sh;
    }
}

// ---------------- helpers ----------------
__device__ __forceinline__ float gelu_f(float x) {
    return 0.5f * x * (1.0f + erff(x * 0.70710678118654752f));
}

__device__ __forceinline__ uint32_t f2tf(float f) {
    uint32_t r;
    asm("cvt.rna.tf32.f32 %0, %1;" : "=r"(r) : "f"(f));
    return r;
}

__device__ __forceinline__ void mma_tf32(float* d, const uint32_t* a, const uint32_t* b) {
    asm volatile(
        "mma.sync.aligned.m16n8k8.row.col.f32.tf32.tf32.f32 "
        "{%0,%1,%2,%3}, {%4,%5,%6,%7}, {%8,%9}, {%0,%1,%2,%3};\n"
        : "+f"(d[0]), "+f"(d[1]), "+f"(d[2]), "+f"(d[3])
        : "r"(a[0]), "r"(a[1]), "r"(a[2]), "r"(a[3]), "r"(b[0]), "r"(b[1]));
}

// fast 2^t on FMA/ALU pipes (no MUFU). t <= ~0 expected; clamped at -126.
__device__ __forceinline__ float exp2_fast(float t) {
    t = fmaxf(t, -126.0f);
    float tr = t + 12582912.0f;               // 1.5 * 2^23 : round-to-nearest-int
    int n = __float_as_int(tr) - 0x4B400000;  // integer part
    float f = t - (tr - 12582912.0f);         // frac in [-0.5, 0.5]
    float p = 0.0096181f;
    p = fmaf(p, f, 0.0555041f);
    p = fmaf(p, f, 0.2402265f);
    p = fmaf(p, f, 0.6931472f);
    p = fmaf(p, f, 1.0f);
    return __int_as_float(__float_as_int(p) + (n << 23));
}

// ---------------- flash attention: QK^T + online softmax + PV fused ----------------
// grid (16 qtiles, 32 bh), 256 threads, dyn smem 106496 B (2 CTAs/SM)
#define FA_SMEM_WORDS 26624
__global__ void __launch_bounds__(256, 2) flash_kernel(
    const float* __restrict__ qkv, float* __restrict__ obuf) {
    extern __shared__ uint32_t sh[];
    uint32_t* Qs = sh;            // [128][68] tf32, pre-scaled
    uint32_t* Ks = sh + 8704;     // [64 d][72 keys]
    uint32_t* Vs = sh + 13312;    // [64 keys][72 d]
    uint32_t* Ps = sh + 17920;    // [128][68] tf32 probs

    int qt = blockIdx.x, bh = blockIdx.y;
    int b = bh >> 4, hd = bh & 15;
    const float* Qg = qkv + (size_t)b * L_ * (3 * C_) + hd * 64;
    const float* Kg = Qg + C_;
    const float* Vg = Qg + 2 * C_;

    int tid = threadIdx.x;
    int w = tid >> 5, lane = tid & 31, g = lane >> 2, tq = lane & 3;
    int wm = w * 16;

    // load Q tile (scale folds 1/sqrt(64) and log2e)
    const float qscale = 0.125f * 1.4426950408889634f;
#pragma unroll
    for (int i = 0; i < 8; i++) {
        int idx = tid + i * 256;            // 0..2047
        int row = idx >> 4, dq = (idx & 15) * 4;
        float4 v = *(const float4*)(Qg + (size_t)(qt * 128 + row) * (3 * C_) + dq);
        uint32_t* p = Qs + row * 68 + dq;
        p[0] = f2tf(v.x * qscale); p[1] = f2tf(v.y * qscale);
        p[2] = f2tf(v.z * qscale); p[3] = f2tf(v.w * qscale);
    }

    float m0 = -1e30f, m1 = -1e30f, l0 = 0.0f, l1 = 0.0f;
    float oacc[8][4];
#pragma unroll
    for (int nt = 0; nt < 8; nt++)
#pragma unroll
        for (int j = 0; j < 4; j++) oacc[nt][j] = 0.0f;

    for (int kt = 0; kt < L_ / 64; kt++) {
        __syncthreads();   // prior iter done reading Ks/Vs (also covers Qs first time)
        // K tile -> Ks[d][key] (transposed)
#pragma unroll
        for (int i = 0; i < 4; i++) {
            int idx = tid + i * 256;        // 0..1023
            int key = idx >> 4, dq = (idx & 15) * 4;
            float4 v = *(const float4*)(Kg + (size_t)(kt * 64 + key) * (3 * C_) + dq);
            Ks[(dq + 0) * 72 + key] = f2tf(v.x);
            Ks[(dq + 1) * 72 + key] = f2tf(v.y);
            Ks[(dq + 2) * 72 + key] = f2tf(v.z);
            Ks[(dq + 3) * 72 + key] = f2tf(v.w);
        }
        // V tile -> Vs[key][d]
#pragma unroll
        for (int i = 0; i < 4; i++) {
            int idx = tid + i * 256;
            int key = idx >> 4, dq = (idx & 15) * 4;
            float4 v = *(const float4*)(Vg + (size_t)(kt * 64 + key) * (3 * C_) + dq);
            uint32_t* p = Vs + key * 72 + dq;
            p[0] = f2tf(v.x); p[1] = f2tf(v.y); p[2] = f2tf(v.z); p[3] = f2tf(v.w);
        }
        __syncthreads();

        // S = Q @ K^T  (warp: 16 rows x 64 keys)
        float sacc[8][4];
#pragma unroll
        for (int nt = 0; nt < 8; nt++)
#pragma unroll
            for (int j = 0; j < 4; j++) sacc[nt][j] = 0.0f;
#pragma unroll
        for (int k0 = 0; k0 < 64; k0 += 8) {
            uint32_t a[4];
            a[0] = Qs[(wm + g) * 68 + k0 + tq];
            a[1] = Qs[(wm + g + 8) * 68 + k0 + tq];
            a[2] = Qs[(wm + g) * 68 + k0 + tq + 4];
            a[3] = Qs[(wm + g + 8) * 68 + k0 + tq + 4];
#pragma unroll
            for (int nt = 0; nt < 8; nt++) {
                uint32_t bf[2];
                bf[0] = Ks[(k0 + tq) * 72 + nt * 8 + g];
                bf[1] = Ks[(k0 + tq + 4) * 72 + nt * 8 + g];
                mma_tf32(sacc[nt], a, bf);
            }
        }

        // online softmax (base-2 domain; scale already folded into Q)
        float rm0 = -1e30f, rm1 = -1e30f;
#pragma unroll
        for (int nt = 0; nt < 8; nt++) {
            rm0 = fmaxf(rm0, fmaxf(sacc[nt][0], sacc[nt][1]));
            rm1 = fmaxf(rm1, fmaxf(sacc[nt][2], sacc[nt][3]));
        }
        rm0 = fmaxf(rm0, __shfl_xor_sync(0xffffffffu, rm0, 1));
        rm0 = fmaxf(rm0, __shfl_xor_sync(0xffffffffu, rm0, 2));
        rm1 = fmaxf(rm1, __shfl_xor_sync(0xffffffffu, rm1, 1));
        rm1 = fmaxf(rm1, __shfl_xor_sync(0xffffffffu, rm1, 2));
        float mn0 = fmaxf(m0, rm0), mn1 = fmaxf(m1, rm1);
        float sc0 = exp2_fast(m0 - mn0), sc1 = exp2_fast(m1 - mn1);
        m0 = mn0; m1 = mn1;
        float rs0 = 0.0f, rs1 = 0.0f;
#pragma unroll
        for (int nt = 0; nt < 8; nt++) {
            float p0 = exp2_fast(sacc[nt][0] - mn0);
            float p1 = exp2_fast(sacc[nt][1] - mn0);
            float p2 = exp2_fast(sacc[nt][2] - mn1);
            float p3 = exp2_fast(sacc[nt][3] - mn1);
            rs0 += p0 + p1;
            rs1 += p2 + p3;
            uint32_t* pr0 = Ps + (wm + g) * 68 + nt * 8 + 2 * tq;
            uint32_t* pr1 = Ps + (wm + g + 8) * 68 + nt * 8 + 2 * tq;
            *(uint2*)pr0 = make_uint2(f2tf(p0), f2tf(p1));
            *(uint2*)pr1 = make_uint2(f2tf(p2), f2tf(p3));
        }
        l0 = l0 * sc0 + rs0;
        l1 = l1 * sc1 + rs1;
#pragma unroll
        for (int nt = 0; nt < 8; nt++) {
            oacc[nt][0] *= sc0; oacc[nt][1] *= sc0;
            oacc[nt][2] *= sc1; oacc[nt][3] *= sc1;
        }
        __syncwarp();

        // O += P @ V  (warp: 16 rows x 64 d)
#pragma unroll
        for (int k0 = 0; k0 < 64; k0 += 8) {
            uint32_t a[4];
            a[0] = Ps[(wm + g) * 68 + k0 + tq];
            a[1] = Ps[(wm + g + 8) * 68 + k0 + tq];
            a[2] = Ps[(wm + g) * 68 + k0 + tq + 4];
            a[3] = Ps[(wm + g + 8) * 68 + k0 + tq + 4];
#pragma unroll
            for (int nt = 0; nt < 8; nt++) {
                uint32_t bf[2];
                bf[0] = Vs[(k0 + tq) * 72 + nt * 8 + g];
                bf[1] = Vs[(k0 + tq + 4) * 72 + nt * 8 + g];
                mma_tf32(oacc[nt], a, bf);
            }
        }
    }

    // finalize
    l0 += __shfl_xor_sync(0xffffffffu, l0, 1);
    l0 += __shfl_xor_sync(0xffffffffu, l0, 2);
    l1 += __shfl_xor_sync(0xffffffffu, l1, 1);
    l1 += __shfl_xor_sync(0xffffffffu, l1, 2);
    float inv0 = 1.0f / l0, inv1 = 1.0f / l1;
    size_t r0 = (size_t)(b * L_ + qt * 128 + wm + g) * C_ + hd * 64;
    size_t r1 = r0 + 8 * C_;
#pragma unroll
    for (int nt = 0; nt < 8; nt++) {
        int c = nt * 8 + 2 * tq;
        *(float2*)(obuf + r0 + c) = make_float2(oacc[nt][0] * inv0, oacc[nt][1] * inv0);
        *(float2*)(obuf + r1 + c) = make_float2(oacc[nt][2] * inv1, oacc[nt][3] * inv1);
    }
}

// ---------------- tf32 tensor-core GEMM ----------------
// EPI: 0 = none, 1 = +bias, 2 = gelu(+bias), 3 = xin + (acc+bias)*gate
template <bool TB, int EPI>
__global__ void __launch_bounds__(256) gemm_tc(
    const float* __restrict__ A, const float* __restrict__ Bm,
    const float* __restrict__ bias, const float* __restrict__ xin,
    const float* __restrict__ gate, float* __restrict__ Cm,
    int M, int N, int K, int lda, int ldb, int ldc) {
    constexpr int BM = 128, BN = 128, BK = 16;
    constexpr int PAD = 8;
    __shared__ uint32_t As[2][BK][BM + PAD];
    __shared__ uint32_t Bs[2][BK][BN + PAD];

    int bm = blockIdx.y * BM, bn = blockIdx.x * BN;
    int tid = threadIdx.x;
    int w = tid >> 5, lane = tid & 31;
    int wm = (w & 1) * 64, wn = (w >> 1) * 32;
    int g = lane >> 2, tq = lane & 3;

    float acc[4][4][4];
#pragma unroll
    for (int i = 0; i < 4; i++)
#pragma unroll
        for (int j = 0; j < 4; j++)
#pragma unroll
            for (int k = 0; k < 4; k++) acc[i][j][k] = 0.0f;

    float4 ra[2], rb[2];

#define LOADG(kt)                                                                  \
    {                                                                              \
        _Pragma("unroll")                                                          \
        for (int it = 0; it < 2; it++) {                                           \
            int ai = tid * 2 + it;                                                 \
            int arow = ai >> 2, aq = ai & 3;                                       \
            ra[it] = *(const float4*)(A + (size_t)(bm + arow) * lda + (kt) + aq * 4); \
            if (TB) {                                                              \
                rb[it] = *(const float4*)(Bm + (size_t)(bn + arow) * ldb + (kt) + aq * 4); \
            } else {                                                               \
                int brow = ai >> 5, bc4 = ai & 31;                                 \
                int col = bn + bc4 * 4;                                            \
                rb[it] = (col < N)                                                 \
                    ? *(const float4*)(Bm + (size_t)((kt) + brow) * ldb + col)     \
                    : make_float4(0.f, 0.f, 0.f, 0.f);                             \
            }                                                                      \
        }                                                                          \
    }

#define STORES(bf)                                                                 \
    {                                                                              \
        _Pragma("unroll")                                                          \
        for (int it = 0; it < 2; it++) {                                           \
            int ai = tid * 2 + it;                                                 \
            int arow = ai >> 2, aq = ai & 3;                                       \
            As[bf][aq * 4 + 0][arow] = f2tf(ra[it].x);                             \
            As[bf][aq * 4 + 1][arow] = f2tf(ra[it].y);                             \
            As[bf][aq * 4 + 2][arow] = f2tf(ra[it].z);                             \
            As[bf][aq * 4 + 3][arow] = f2tf(ra[it].w);                             \
            if (TB) {                                                              \
                Bs[bf][aq * 4 + 0][arow] = f2tf(rb[it].x);                         \
                Bs[bf][aq * 4 + 1][arow] = f2tf(rb[it].y);                         \
                Bs[bf][aq * 4 + 2][arow] = f2tf(rb[it].z);                         \
                Bs[bf][aq * 4 + 3][arow] = f2tf(rb[it].w);                         \
            } else {                                                               \
                int brow = ai >> 5, bc4 = ai & 31;                                 \
                Bs[bf][brow][bc4 * 4 + 0] = f2tf(rb[it].x);                        \
                Bs[bf][brow][bc4 * 4 + 1] = f2tf(rb[it].y);                        \
                Bs[bf][brow][bc4 * 4 + 2] = f2tf(rb[it].z);                        \
                Bs[bf][brow][bc4 * 4 + 3] = f2tf(rb[it].w);                        \
            }                                                                      \
        }                                                                          \
    }

#define COMP(bf)                                                                   \
    {                                                                              \
        _Pragma("unroll")                                                          \
        for (int k0 = 0; k0 < BK; k0 += 8) {                                       \
            uint32_t af[4][4], bfr[4][2];                                          \
            _Pragma("unroll")                                                      \
            for (int mt = 0; mt < 4; mt++) {                                       \
                int r = wm + mt * 16 + g;                                          \
                af[mt][0] = As[bf][k0 + tq][r];                                    \
                af[mt][1] = As[bf][k0 + tq][r + 8];                                \
                af[mt][2] = As[bf][k0 + tq + 4][r];                                \
                af[mt][3] = As[bf][k0 + tq + 4][r + 8];                            \
            }                                                                      \
            _Pragma("unroll")                                                      \
            for (int nt = 0; nt < 4; nt++) {                                       \
                int c = wn + nt * 8 + g;                                           \
                bfr[nt][0] = Bs[bf][k0 + tq][c];                                   \
                bfr[nt][1] = Bs[bf][k0 + tq + 4][c];                               \
            }                                                                      \
            _Pragma("unroll")                                                      \
            for (int mt = 0; mt < 4; mt++)                                         \
                _Pragma("unroll")                                                  \
                for (int nt = 0; nt < 4; nt++)                                     \
                    mma_tf32(acc[mt][nt], af[mt], bfr[nt]);                        \
        }                                                                          \
    }

    LOADG(0);
    STORES(0);
    __syncthreads();
    int buf = 0;
    for (int kt = BK; kt < K; kt += BK) {
        LOADG(kt);
        COMP(buf);
        __syncthreads();
        STORES(buf ^ 1);
        __syncthreads();
        buf ^= 1;
    }
    COMP(buf);

#pragma unroll
    for (int mt = 0; mt < 4; mt++) {
#pragma unroll
        for (int i = 0; i < 2; i++) {
            int r = bm + wm + mt * 16 + g + i * 8;
            int bb = r >> 11;
#pragma unroll
            for (int nt = 0; nt < 4; nt++) {
                int c = bn + wn + nt * 8 + tq * 2;
                if (c < N) {
                    float v0 = acc[mt][nt][i * 2 + 0];
                    float v1 = acc[mt][nt][i * 2 + 1];
                    if (EPI >= 1) { v0 += bias[c]; v1 += bias[c + 1]; }
                    if (EPI == 2) { v0 = gelu_f(v0); v1 = gelu_f(v1); }
                    if (EPI == 3) {
                        v0 = xin[(size_t)r * ldc + c]     + v0 * gate[bb * (6 * C_) + c];
                        v1 = xin[(size_t)r * ldc + c + 1] + v1 * gate[bb * (6 * C_) + c + 1];
                    }
                    Cm[(size_t)r * ldc + c]     = v0;
                    Cm[(size_t)r * ldc + c + 1] = v1;
                }
            }
        }
    }
#undef LOADG
#undef STORES
#undef COMP
}

// ---------------- launch ----------------
extern "C" void kernel_launch(void* const* d_in, const int* in_sizes, int n_in,
                              void* d_out, int out_size) {
    const float* feats  = (const float*)d_in[0];
    const float* mod    = (const float*)d_in[1];
    const float* w_mod  = (const float*)d_in[2];
    const float* b_mod  = (const float*)d_in[3];
    const float* w_qkv  = (const float*)d_in[4];
    const float* b_qkv  = (const float*)d_in[5];
    const float* w_proj = (const float*)d_in[6];
    const float* b_proj = (const float*)d_in[7];
    const float* w_fc1  = (const float*)d_in[8];
    const float* b_fc1  = (const float*)d_in[9];
    const float* w_fc2  = (const float*)d_in[10];
    const float* b_fc2  = (const float*)d_in[11];
    float* out = (float*)d_out;

    float *mod6, *h, *qkv, *obuf, *xbuf, *gbuf;
    cudaGetSymbolAddress((void**)&mod6, g_mod6);
    cudaGetSymbolAddress((void**)&h,    g_h);
    cudaGetSymbolAddress((void**)&qkv,  g_qkv);
    cudaGetSymbolAddress((void**)&obuf, g_o);
    cudaGetSymbolAddress((void**)&xbuf, g_x);
    cudaGetSymbolAddress((void**)&gbuf, g_g);

    // 1. adaLN modulation vector
    mod_kernel<<<dim3(6 * C_ / 256, B_), 256>>>(mod, w_mod, b_mod, mod6);

    // 2. LN1 + (shift_a, scale_a)
    ln_mod_kernel<<<M_, 256>>>(feats, h, mod6, 0, 1);

    // 3. qkv = h @ w_qkv + b_qkv
    gemm_tc<false, 1><<<dim3(24, 32), 256>>>(
        h, w_qkv, b_qkv, nullptr, nullptr, qkv,
        M_, 3 * C_, C_, C_, 3 * C_, 3 * C_);

    // 4. fused flash attention -> obuf
    cudaFuncSetAttribute(flash_kernel, cudaFuncAttributeMaxDynamicSharedMemorySize,
                         FA_SMEM_WORDS * 4);
    flash_kernel<<<dim3(16, 32), 256, FA_SMEM_WORDS * 4>>>(qkv, obuf);

    // 5. x = feats + (O @ w_proj + b_proj) * gate_a
    gemm_tc<false, 3><<<dim3(8, 32), 256>>>(
        obuf, w_proj, b_proj, feats, mod6 + 2 * C_, xbuf,
        M_, C_, C_, C_, C_, C_);

    // 6. LN2 + (shift_m, scale_m)
    ln_mod_kernel<<<M_, 256>>>(xbuf, h, mod6, 3, 4);

    // 7. g = gelu(h @ w_fc1 + b_fc1)
    gemm_tc<false, 2><<<dim3(32, 32), 256>>>(
        h, w_fc1, b_fc1, nullptr, nullptr, gbuf,
        M_, 4 * C_, C_, C_, 4 * C_, 4 * C_);

    // 8. out = x + (g @ w_fc2 + b_fc2) * gate_m
    gemm_tc<false, 3><<<dim3(8, 32), 256>>>(
        gbuf, w_fc2, b_fc2, xbuf, mod6 + 5 * C_, out,
        M_, C_, 4 * C_, 4 * C_, C_, C_);
}

// round 4
// speedup vs baseline: 3.9145x; 1.3127x over previous
#include <cuda_runtime.h>
#include <math.h>
#include <stdint.h>

#define B_ 2
#define L_ 2048
#define C_ 1024
#define H_ 16
#define M_ 4096   // B_*L_

// ---------------- scratch (static device globals; no allocation) ----------------
__device__ float g_mod6[B_ * 6 * C_];
__device__ float g_h[M_ * C_];
__device__ float g_qkv[M_ * 3 * C_];
__device__ float g_o[M_ * C_];
__device__ float g_x[M_ * C_];
__device__ float g_g[M_ * 4 * C_];

// ---------------- cp.async helpers ----------------
__device__ __forceinline__ void cp16(uint32_t dst, const void* src) {
    asm volatile("cp.async.cg.shared.global [%0], [%1], 16;\n" :: "r"(dst), "l"(src));
}
#define CP_COMMIT() asm volatile("cp.async.commit_group;\n" ::: "memory")
#define CP_WAIT(n)  asm volatile("cp.async.wait_group %0;\n" :: "n"(n) : "memory")

// ---------------- adaLN modulation: silu(mod) @ w_mod + b_mod ----------------
__global__ void mod_kernel(const float* __restrict__ mod,
                           const float* __restrict__ w,
                           const float* __restrict__ b,
                           float* __restrict__ out) {
    __shared__ float sm[C_];
    int batch = blockIdx.y;
    const float* mrow = mod + batch * C_;
    for (int i = threadIdx.x; i < C_; i += blockDim.x) {
        float v = mrow[i];
        sm[i] = v / (1.0f + expf(-v));
    }
    __syncthreads();
    int n = blockIdx.x * blockDim.x + threadIdx.x;
    float acc = b[n];
#pragma unroll 4
    for (int k = 0; k < C_; k++)
        acc += sm[k] * w[k * (6 * C_) + n];
    out[batch * (6 * C_) + n] = acc;
}

// ---------------- LayerNorm + shift/scale modulation ----------------
__global__ void ln_mod_kernel(const float* __restrict__ x, float* __restrict__ out,
                              const float* __restrict__ mod6, int shiftChunk, int scaleChunk) {
    __shared__ float red[8];
    __shared__ float bc[2];
    int r = blockIdx.x;
    int b = r >> 11;
    const float* xr = x + (size_t)r * C_;
    int t = threadIdx.x;
    float v[4];
    float s = 0.0f;
#pragma unroll
    for (int i = 0; i < 4; i++) { v[i] = xr[t + 256 * i]; s += v[i]; }
    for (int o = 16; o > 0; o >>= 1) s += __shfl_xor_sync(0xffffffffu, s, o);
    if ((t & 31) == 0) red[t >> 5] = s;
    __syncthreads();
    if (t == 0) {
        float tot = 0.0f;
        for (int i = 0; i < 8; i++) tot += red[i];
        bc[0] = tot * (1.0f / C_);
    }
    __syncthreads();
    float mean = bc[0];
    float q = 0.0f;
#pragma unroll
    for (int i = 0; i < 4; i++) { float d = v[i] - mean; q += d * d; }
    for (int o = 16; o > 0; o >>= 1) q += __shfl_xor_sync(0xffffffffu, q, o);
    __syncthreads();
    if ((t & 31) == 0) red[t >> 5] = q;
    __syncthreads();
    if (t == 0) {
        float tot = 0.0f;
        for (int i = 0; i < 8; i++) tot += red[i];
        bc[1] = rsqrtf(tot * (1.0f / C_) + 1e-6f);
    }
    __syncthreads();
    float rstd = bc[1];
    const float* mb = mod6 + b * (6 * C_);
    float* orow = out + (size_t)r * C_;
#pragma unroll
    for (int i = 0; i < 4; i++) {
        int c = t + 256 * i;
        float sc = mb[scaleChunk * C_ + c];
        float sh = mb[shiftChunk * C_ + c];
        orow[c] = (v[i] - mean) * rstd * (1.0f + sc) + sh;
    }
}

// ---------------- helpers ----------------
__device__ __forceinline__ float gelu_f(float x) {
    return 0.5f * x * (1.0f + erff(x * 0.70710678118654752f));
}

__device__ __forceinline__ void mma_tf32(float* d, const uint32_t* a, const uint32_t* b) {
    asm volatile(
        "mma.sync.aligned.m16n8k8.row.col.f32.tf32.tf32.f32 "
        "{%0,%1,%2,%3}, {%4,%5,%6,%7}, {%8,%9}, {%0,%1,%2,%3};\n"
        : "+f"(d[0]), "+f"(d[1]), "+f"(d[2]), "+f"(d[3])
        : "r"(a[0]), "r"(a[1]), "r"(a[2]), "r"(a[3]), "r"(b[0]), "r"(b[1]));
}

// fast 2^t on FMA/ALU pipes (no MUFU)
__device__ __forceinline__ float exp2_fast(float t) {
    t = fmaxf(t, -126.0f);
    float tr = t + 12582912.0f;
    int n = __float_as_int(tr) - 0x4B400000;
    float f = t - (tr - 12582912.0f);
    float p = 0.0096181f;
    p = fmaf(p, f, 0.0555041f);
    p = fmaf(p, f, 0.2402265f);
    p = fmaf(p, f, 0.6931472f);
    p = fmaf(p, f, 1.0f);
    return __int_as_float(__float_as_int(p) + (n << 23));
}

// ---------------- flash attention v2: Q in regs, cp.async double-buffered K/V ----------------
// smem words: K 2*64*68=8704 | V 2*64*72=9216 | P 128*68=8704  -> 26624 w = 106496 B
#define FA_SMEM_BYTES 106496
__global__ void __launch_bounds__(256, 2) flash_kernel(
    const float* __restrict__ qkv, float* __restrict__ obuf) {
    extern __shared__ uint32_t sh[];
    uint32_t* Ps = sh + 17920;

    int qt = blockIdx.x, bh = blockIdx.y;
    int b = bh >> 4, hd = bh & 15;
    const float* Qg = qkv + (size_t)b * L_ * (3 * C_) + hd * 64;
    const float* Kg = Qg + C_;
    const float* Vg = Qg + 2 * C_;

    int tid = threadIdx.x;
    int w = tid >> 5, lane = tid & 31, g = lane >> 2, tq = lane & 3;
    int wm = w * 16;
    uint32_t sbase = (uint32_t)__cvta_generic_to_shared(sh);

    // per-warp Q fragments in registers (raw f32 bits)
    uint32_t qf[8][4];
    {
        const float* q0 = Qg + (size_t)(qt * 128 + wm + g) * (3 * C_);
        const float* q1 = q0 + (size_t)8 * (3 * C_);
#pragma unroll
        for (int k0 = 0; k0 < 8; k0++) {
            qf[k0][0] = __float_as_uint(q0[k0 * 8 + tq]);
            qf[k0][1] = __float_as_uint(q1[k0 * 8 + tq]);
            qf[k0][2] = __float_as_uint(q0[k0 * 8 + tq + 4]);
            qf[k0][3] = __float_as_uint(q1[k0 * 8 + tq + 4]);
        }
    }

#define ISSUE_KV(kt, bf)                                                           \
    {                                                                              \
        _Pragma("unroll")                                                          \
        for (int i = 0; i < 4; i++) {                                              \
            int ci = tid + i * 256;                                                \
            int row = ci >> 4, q = ci & 15;                                        \
            cp16(sbase + ((bf) * 4352 + row * 68 + q * 4) * 4,                     \
                 Kg + (size_t)((kt) * 64 + row) * (3 * C_) + q * 4);               \
        }                                                                          \
        _Pragma("unroll")                                                          \
        for (int i = 0; i < 4; i++) {                                              \
            int ci = tid + i * 256;                                                \
            int row = ci >> 4, q = ci & 15;                                        \
            cp16(sbase + (8704 + (bf) * 4608 + row * 72 + q * 4) * 4,              \
                 Vg + (size_t)((kt) * 64 + row) * (3 * C_) + q * 4);               \
        }                                                                          \
    }

    ISSUE_KV(0, 0);
    CP_COMMIT();

    const float SC = 0.125f * 1.4426950408889634f;   // 1/sqrt(64) * log2(e)
    float m0 = -1e30f, m1 = -1e30f, l0 = 0.0f, l1 = 0.0f;
    float oacc[8][4];
#pragma unroll
    for (int nt = 0; nt < 8; nt++)
#pragma unroll
        for (int j = 0; j < 4; j++) oacc[nt][j] = 0.0f;

    for (int kt = 0; kt < L_ / 64; kt++) {
        int bf = kt & 1;
        CP_WAIT(0);
        __syncthreads();
        if (kt + 1 < L_ / 64) { ISSUE_KV(kt + 1, bf ^ 1); }
        CP_COMMIT();

        uint32_t* Kb = sh + bf * 4352;
        uint32_t* Vb = sh + 8704 + bf * 4608;

        // S = Q @ K^T
        float sacc[8][4];
#pragma unroll
        for (int nt = 0; nt < 8; nt++)
#pragma unroll
            for (int j = 0; j < 4; j++) sacc[nt][j] = 0.0f;
#pragma unroll
        for (int k0 = 0; k0 < 8; k0++) {
#pragma unroll
            for (int nt = 0; nt < 8; nt++) {
                uint32_t bfr[2];
                bfr[0] = Kb[(nt * 8 + g) * 68 + k0 * 8 + tq];
                bfr[1] = Kb[(nt * 8 + g) * 68 + k0 * 8 + tq + 4];
                mma_tf32(sacc[nt], qf[k0], bfr);
            }
        }

        // online softmax (scale folded into exp2 argument)
        float rm0 = -1e30f, rm1 = -1e30f;
#pragma unroll
        for (int nt = 0; nt < 8; nt++) {
            rm0 = fmaxf(rm0, fmaxf(sacc[nt][0], sacc[nt][1]));
            rm1 = fmaxf(rm1, fmaxf(sacc[nt][2], sacc[nt][3]));
        }
        rm0 = fmaxf(rm0, __shfl_xor_sync(0xffffffffu, rm0, 1));
        rm0 = fmaxf(rm0, __shfl_xor_sync(0xffffffffu, rm0, 2));
        rm1 = fmaxf(rm1, __shfl_xor_sync(0xffffffffu, rm1, 1));
        rm1 = fmaxf(rm1, __shfl_xor_sync(0xffffffffu, rm1, 2));
        float mn0 = fmaxf(m0, rm0), mn1 = fmaxf(m1, rm1);
        float sc0 = exp2_fast((m0 - mn0) * SC), sc1 = exp2_fast((m1 - mn1) * SC);
        m0 = mn0; m1 = mn1;
        float rs0 = 0.0f, rs1 = 0.0f;
#pragma unroll
        for (int nt = 0; nt < 8; nt++) {
            float p0 = exp2_fast((sacc[nt][0] - mn0) * SC);
            float p1 = exp2_fast((sacc[nt][1] - mn0) * SC);
            float p2 = exp2_fast((sacc[nt][2] - mn1) * SC);
            float p3 = exp2_fast((sacc[nt][3] - mn1) * SC);
            rs0 += p0 + p1;
            rs1 += p2 + p3;
            uint32_t* pr0 = Ps + (wm + g) * 68 + nt * 8 + 2 * tq;
            uint32_t* pr1 = Ps + (wm + g + 8) * 68 + nt * 8 + 2 * tq;
            *(uint2*)pr0 = make_uint2(__float_as_uint(p0), __float_as_uint(p1));
            *(uint2*)pr1 = make_uint2(__float_as_uint(p2), __float_as_uint(p3));
        }
        l0 = l0 * sc0 + rs0;
        l1 = l1 * sc1 + rs1;
#pragma unroll
        for (int nt = 0; nt < 8; nt++) {
            oacc[nt][0] *= sc0; oacc[nt][1] *= sc0;
            oacc[nt][2] *= sc1; oacc[nt][3] *= sc1;
        }
        __syncwarp();

        // O += P @ V
#pragma unroll
        for (int k0 = 0; k0 < 8; k0++) {
            uint32_t a[4];
            a[0] = Ps[(wm + g) * 68 + k0 * 8 + tq];
            a[1] = Ps[(wm + g + 8) * 68 + k0 * 8 + tq];
            a[2] = Ps[(wm + g) * 68 + k0 * 8 + tq + 4];
            a[3] = Ps[(wm + g + 8) * 68 + k0 * 8 + tq + 4];
#pragma unroll
            for (int nt = 0; nt < 8; nt++) {
                uint32_t bfr[2];
                bfr[0] = Vb[(k0 * 8 + tq) * 72 + nt * 8 + g];
                bfr[1] = Vb[(k0 * 8 + tq + 4) * 72 + nt * 8 + g];
                mma_tf32(oacc[nt], a, bfr);
            }
        }
        __syncwarp();
    }
#undef ISSUE_KV

    l0 += __shfl_xor_sync(0xffffffffu, l0, 1);
    l0 += __shfl_xor_sync(0xffffffffu, l0, 2);
    l1 += __shfl_xor_sync(0xffffffffu, l1, 1);
    l1 += __shfl_xor_sync(0xffffffffu, l1, 2);
    float inv0 = 1.0f / l0, inv1 = 1.0f / l1;
    size_t r0 = (size_t)(b * L_ + qt * 128 + wm + g) * C_ + hd * 64;
    size_t r1 = r0 + 8 * C_;
#pragma unroll
    for (int nt = 0; nt < 8; nt++) {
        int c = nt * 8 + 2 * tq;
        *(float2*)(obuf + r0 + c) = make_float2(oacc[nt][0] * inv0, oacc[nt][1] * inv0);
        *(float2*)(obuf + r1 + c) = make_float2(oacc[nt][2] * inv1, oacc[nt][3] * inv1);
    }
}

// ---------------- dense tf32 GEMM: 3-stage cp.async pipeline ----------------
// smem: A [3][128][20] + B [3][16][136]  -> 14208 w = 56832 B
#define GE_SMEM_BYTES 56832
// EPI: 1 = +bias, 2 = gelu(+bias), 3 = xin + (acc+bias)*gate
template <int EPI>
__global__ void __launch_bounds__(256, 2) gemm_tc(
    const float* __restrict__ A, const float* __restrict__ Bm,
    const float* __restrict__ bias, const float* __restrict__ xin,
    const float* __restrict__ gate, float* __restrict__ Cm,
    int N, int K, int lda, int ldb, int ldc) {
    extern __shared__ uint32_t smem[];
    uint32_t* As = smem;            // [3][128][20]
    uint32_t* Bs = smem + 3 * 2560; // [3][16][136]

    int bm = blockIdx.y * 128, bn = blockIdx.x * 128;
    int tid = threadIdx.x;
    int w = tid >> 5, lane = tid & 31;
    int wm = (w & 1) * 64, wn = (w >> 1) * 32;
    int g = lane >> 2, tq = lane & 3;
    uint32_t sA = (uint32_t)__cvta_generic_to_shared(As);
    uint32_t sB = (uint32_t)__cvta_generic_to_shared(Bs);

#define GISSUE(s, kt)                                                              \
    {                                                                              \
        _Pragma("unroll")                                                          \
        for (int it = 0; it < 2; it++) {                                           \
            int ci = tid + it * 256;                                               \
            int row = ci >> 2, q = ci & 3;                                         \
            cp16(sA + ((s) * 2560 + row * 20 + q * 4) * 4,                         \
                 A + (size_t)(bm + row) * lda + (kt) * 16 + q * 4);                \
        }                                                                          \
        _Pragma("unroll")                                                          \
        for (int it = 0; it < 2; it++) {                                           \
            int ci = tid + it * 256;                                               \
            int row = ci >> 5, q = ci & 31;                                        \
            cp16(sB + ((s) * 2176 + row * 136 + q * 4) * 4,                        \
                 Bm + (size_t)((kt) * 16 + row) * ldb + bn + q * 4);               \
        }                                                                          \
    }

    int nk = K / 16;
    GISSUE(0, 0); CP_COMMIT();
    GISSUE(1, 1); CP_COMMIT();

    float acc[4][4][4];
#pragma unroll
    for (int i = 0; i < 4; i++)
#pragma unroll
        for (int j = 0; j < 4; j++)
#pragma unroll
            for (int k = 0; k < 4; k++) acc[i][j][k] = 0.0f;

    for (int kt = 0; kt < nk; kt++) {
        int rs = kt % 3;
        CP_WAIT(1);
        __syncthreads();
        if (kt + 2 < nk) { GISSUE((kt + 2) % 3, kt + 2); }
        CP_COMMIT();

        const uint32_t* Ab = As + rs * 2560;
        const uint32_t* Bb = Bs + rs * 2176;
#pragma unroll
        for (int k0 = 0; k0 < 16; k0 += 8) {
            uint32_t af[4][4], bfr[4][2];
#pragma unroll
            for (int mt = 0; mt < 4; mt++) {
                int r = wm + mt * 16 + g;
                af[mt][0] = Ab[r * 20 + k0 + tq];
                af[mt][1] = Ab[(r + 8) * 20 + k0 + tq];
                af[mt][2] = Ab[r * 20 + k0 + tq + 4];
                af[mt][3] = Ab[(r + 8) * 20 + k0 + tq + 4];
            }
#pragma unroll
            for (int nt = 0; nt < 4; nt++) {
                int c = wn + nt * 8 + g;
                bfr[nt][0] = Bb[(k0 + tq) * 136 + c];
                bfr[nt][1] = Bb[(k0 + tq + 4) * 136 + c];
            }
#pragma unroll
            for (int mt = 0; mt < 4; mt++)
#pragma unroll
                for (int nt = 0; nt < 4; nt++)
                    mma_tf32(acc[mt][nt], af[mt], bfr[nt]);
        }
    }
#undef GISSUE

    // epilogue
#pragma unroll
    for (int mt = 0; mt < 4; mt++) {
#pragma unroll
        for (int i = 0; i < 2; i++) {
            int r = bm + wm + mt * 16 + g + i * 8;
            int bb = r >> 11;
#pragma unroll
            for (int nt = 0; nt < 4; nt++) {
                int c = bn + wn + nt * 8 + tq * 2;
                float v0 = acc[mt][nt][i * 2 + 0];
                float v1 = acc[mt][nt][i * 2 + 1];
                if (EPI >= 1) { v0 += bias[c]; v1 += bias[c + 1]; }
                if (EPI == 2) { v0 = gelu_f(v0); v1 = gelu_f(v1); }
                if (EPI == 3) {
                    v0 = xin[(size_t)r * ldc + c]     + v0 * gate[bb * (6 * C_) + c];
                    v1 = xin[(size_t)r * ldc + c + 1] + v1 * gate[bb * (6 * C_) + c + 1];
                }
                Cm[(size_t)r * ldc + c]     = v0;
                Cm[(size_t)r * ldc + c + 1] = v1;
            }
        }
    }
}

// ---------------- launch ----------------
extern "C" void kernel_launch(void* const* d_in, const int* in_sizes, int n_in,
                              void* d_out, int out_size) {
    const float* feats  = (const float*)d_in[0];
    const float* mod    = (const float*)d_in[1];
    const float* w_mod  = (const float*)d_in[2];
    const float* b_mod  = (const float*)d_in[3];
    const float* w_qkv  = (const float*)d_in[4];
    const float* b_qkv  = (const float*)d_in[5];
    const float* w_proj = (const float*)d_in[6];
    const float* b_proj = (const float*)d_in[7];
    const float* w_fc1  = (const float*)d_in[8];
    const float* b_fc1  = (const float*)d_in[9];
    const float* w_fc2  = (const float*)d_in[10];
    const float* b_fc2  = (const float*)d_in[11];
    float* out = (float*)d_out;

    float *mod6, *h, *qkv, *obuf, *xbuf, *gbuf;
    cudaGetSymbolAddress((void**)&mod6, g_mod6);
    cudaGetSymbolAddress((void**)&h,    g_h);
    cudaGetSymbolAddress((void**)&qkv,  g_qkv);
    cudaGetSymbolAddress((void**)&obuf, g_o);
    cudaGetSymbolAddress((void**)&xbuf, g_x);
    cudaGetSymbolAddress((void**)&gbuf, g_g);

    cudaFuncSetAttribute(flash_kernel, cudaFuncAttributeMaxDynamicSharedMemorySize, FA_SMEM_BYTES);
    cudaFuncSetAttribute(gemm_tc<1>, cudaFuncAttributeMaxDynamicSharedMemorySize, GE_SMEM_BYTES);
    cudaFuncSetAttribute(gemm_tc<2>, cudaFuncAttributeMaxDynamicSharedMemorySize, GE_SMEM_BYTES);
    cudaFuncSetAttribute(gemm_tc<3>, cudaFuncAttributeMaxDynamicSharedMemorySize, GE_SMEM_BYTES);

    // 1. adaLN modulation vector
    mod_kernel<<<dim3(6 * C_ / 256, B_), 256>>>(mod, w_mod, b_mod, mod6);

    // 2. LN1 + (shift_a, scale_a)
    ln_mod_kernel<<<M_, 256>>>(feats, h, mod6, 0, 1);

    // 3. qkv = h @ w_qkv + b_qkv
    gemm_tc<1><<<dim3(24, 32), 256, GE_SMEM_BYTES>>>(
        h, w_qkv, b_qkv, nullptr, nullptr, qkv, 3 * C_, C_, C_, 3 * C_, 3 * C_);

    // 4. fused flash attention -> obuf
    flash_kernel<<<dim3(16, 32), 256, FA_SMEM_BYTES>>>(qkv, obuf);

    // 5. x = feats + (O @ w_proj + b_proj) * gate_a
    gemm_tc<3><<<dim3(8, 32), 256, GE_SMEM_BYTES>>>(
        obuf, w_proj, b_proj, feats, mod6 + 2 * C_, xbuf, C_, C_, C_, C_, C_);

    // 6. LN2 + (shift_m, scale_m)
    ln_mod_kernel<<<M_, 256>>>(xbuf, h, mod6, 3, 4);

    // 7. g = gelu(h @ w_fc1 + b_fc1)
    gemm_tc<2><<<dim3(32, 32), 256, GE_SMEM_BYTES>>>(
        h, w_fc1, b_fc1, nullptr, nullptr, gbuf, 4 * C_, C_, C_, 4 * C_, 4 * C_);

    // 8. out = x + (g @ w_fc2 + b_fc2) * gate_m
    gemm_tc<3><<<dim3(8, 32), 256, GE_SMEM_BYTES>>>(
        gbuf, w_fc2, b_fc2, xbuf, mod6 + 5 * C_, out, C_, 4 * C_, 4 * C_, C_, C_);
}